// round 1
// baseline (speedup 1.0000x reference)
#include <cuda_runtime.h>
#include <math.h>

#define Bn 4
#define GLn 4
#define GFn 128
#define Nn 1024
#define CSn 32
#define CNn 16
#define NAn 16
#define Sn 512
#define Rn 128     // GL*CS  (primary capsule rows)
#define K1n 512    // GL*GF  (primary contraction)
#define IKn 128    // CS*GL  (routing contraction dim)
#define JUn 512    // CN*CS
#define MS 8       // m-splits for T gemm

// -------- scratch (device globals; no allocations anywhere) --------
__device__ float g_u[Bn*Rn*Nn];            // primary caps pre-squash, [b][r=128][n=1024]
__device__ float g_scale[Bn*GLn];          // squash factor per (b, GL-group)
__device__ float g_W1[Bn*JUn*IKn];         // c-weighted Wg: [b][ju=512][ik=128]
__device__ float g_S[Bn*Nn*JUn];           // routing s (pre-squash)
__device__ float g_V[Bn*Nn*JUn];           // routing v
__device__ float g_T[Bn*MS*IKn*JUn];       // partial P^T V
__device__ float g_blog[Bn*CSn*CNn];       // routing logits b, [b][i=32][j=16]
__device__ float g_gpart[Bn*8*JUn];        // column-sum partials of final v (for g)
__device__ float g_va[Bn*NAn*CSn];         // aspect routing output

// ---------------- init ----------------
__global__ void k_init(){
    int i = blockIdx.x*blockDim.x + threadIdx.x;
    if (i < Bn*CSn*CNn) g_blog[i] = 0.f;
}

// ---------------- primary capsules: u = Wp[128,512] @ x[b][512,1024] + bp ----------------
__global__ __launch_bounds__(256) void k_primary(const float* __restrict__ Wp,
                                                 const float* __restrict__ bp,
                                                 const float* __restrict__ X){
    __shared__ float shA[16][65];
    __shared__ float shB[16][65];
    int b = blockIdx.z;
    int m0 = blockIdx.y*64, n0 = blockIdx.x*64;
    const float* Xb = X + (size_t)b*K1n*Nn;
    int tid = threadIdx.x;
    int tx = tid & 15, ty = tid >> 4;
    float acc[4][4] = {};
    for (int k0 = 0; k0 < K1n; k0 += 16){
        for (int e = tid; e < 64*16; e += 256){
            int m = e >> 4, k = e & 15;
            shA[k][m] = Wp[(m0+m)*K1n + k0 + k];
        }
        for (int e = tid; e < 16*64; e += 256){
            int k = e >> 6, n = e & 63;
            shB[k][n] = Xb[(size_t)(k0+k)*Nn + n0 + n];
        }
        __syncthreads();
        #pragma unroll
        for (int kk = 0; kk < 16; kk++){
            float a[4], c[4];
            #pragma unroll
            for (int i = 0; i < 4; i++) a[i] = shA[kk][ty*4+i];
            #pragma unroll
            for (int j = 0; j < 4; j++) c[j] = shB[kk][tx*4+j];
            #pragma unroll
            for (int i = 0; i < 4; i++)
                #pragma unroll
                for (int j = 0; j < 4; j++)
                    acc[i][j] += a[i]*c[j];
        }
        __syncthreads();
    }
    #pragma unroll
    for (int i = 0; i < 4; i++){
        int m = m0 + ty*4 + i;
        float bias = bp[m];
        #pragma unroll
        for (int j = 0; j < 4; j++)
            g_u[(size_t)b*Rn*Nn + (size_t)m*Nn + n0 + tx*4 + j] = acc[i][j] + bias;
    }
}

// ---------------- squash factor per (b, GL group): sqrt(msq)/(1+msq) over 32768 elems ----------------
__global__ __launch_bounds__(256) void k_msq(){
    int bg = blockIdx.x;                       // b*4+g
    const float* p = g_u + (size_t)bg*(CSn*Nn);
    __shared__ float red[256];
    int tid = threadIdx.x;
    float s = 0.f;
    for (int e = tid; e < CSn*Nn; e += 256){ float v = p[e]; s += v*v; }
    red[tid] = s; __syncthreads();
    for (int off = 128; off; off >>= 1){
        if (tid < off) red[tid] += red[tid+off];
        __syncthreads();
    }
    if (tid == 0){ float m = red[0]; g_scale[bg] = sqrtf(m)/(1.f+m); }
}

// ---------------- W1[ju][ik] = softmax_j(blog)[i][j] * Wg[i][j][u][k], col ik = k*32+i ----------------
__global__ __launch_bounds__(256) void k_route_w(const float* __restrict__ Wg){
    int b = blockIdx.x, tid = threadIdx.x;
    __shared__ float c[CSn][CNn];
    if (tid < CSn){
        int i = tid;
        float row[CNn], mx = -1e30f;
        #pragma unroll
        for (int j = 0; j < CNn; j++){ row[j] = g_blog[b*CSn*CNn + i*CNn + j]; mx = fmaxf(mx, row[j]); }
        float sum = 0.f;
        #pragma unroll
        for (int j = 0; j < CNn; j++){ row[j] = expf(row[j]-mx); sum += row[j]; }
        float inv = 1.f/sum;
        #pragma unroll
        for (int j = 0; j < CNn; j++) c[i][j] = row[j]*inv;
    }
    __syncthreads();
    for (int e = tid; e < JUn*IKn; e += 256){
        int n = e >> 7, col = e & 127;
        int j = n >> 5, u = n & 31, k = col >> 5, i = col & 31;
        g_W1[(size_t)b*JUn*IKn + e] = c[i][j]*Wg[((i*CNn+j)*CSn+u)*GLn + k];
    }
}

// ---------------- s GEMM (NT): S[m][ju] = sum_ik (sc_m * U[m][ik]) * W1[ju][ik] ----------------
__global__ __launch_bounds__(256) void k_route_s(){
    __shared__ float shA[16][65];
    __shared__ float shB[16][65];
    int b = blockIdx.z;
    int m0 = blockIdx.y*64, n0 = blockIdx.x*64;
    const float* U = g_u + (size_t)b*Nn*IKn;          // viewed as [1024][128]
    const float* W = g_W1 + (size_t)b*JUn*IKn;
    float sc = g_scale[b*GLn + (m0 >> 8)];
    int tid = threadIdx.x;
    int tx = tid & 15, ty = tid >> 4;
    float acc[4][4] = {};
    for (int k0 = 0; k0 < IKn; k0 += 16){
        for (int e = tid; e < 64*16; e += 256){
            int m = e >> 4, k = e & 15;
            shA[k][m] = U[(size_t)(m0+m)*IKn + k0 + k]*sc;
        }
        for (int e = tid; e < 64*16; e += 256){
            int n = e >> 4, k = e & 15;
            shB[k][n] = W[(size_t)(n0+n)*IKn + k0 + k];
        }
        __syncthreads();
        #pragma unroll
        for (int kk = 0; kk < 16; kk++){
            float a[4], c[4];
            #pragma unroll
            for (int i = 0; i < 4; i++) a[i] = shA[kk][ty*4+i];
            #pragma unroll
            for (int j = 0; j < 4; j++) c[j] = shB[kk][tx*4+j];
            #pragma unroll
            for (int i = 0; i < 4; i++)
                #pragma unroll
                for (int j = 0; j < 4; j++)
                    acc[i][j] += a[i]*c[j];
        }
        __syncthreads();
    }
    #pragma unroll
    for (int i = 0; i < 4; i++)
        #pragma unroll
        for (int j = 0; j < 4; j++)
            g_S[(size_t)b*Nn*JUn + (size_t)(m0+ty*4+i)*JUn + n0 + tx*4 + j] = acc[i][j];
}

// ---------------- squash over J (iters 0,1): V[m][j*32+u] = S * sqrt(msq_mu)/(1+msq_mu) ----------------
__global__ __launch_bounds__(256) void k_squash(){
    int b = blockIdx.y; int m0 = blockIdx.x*128;
    const float* Sp = g_S + (size_t)b*Nn*JUn + (size_t)m0*JUn;
    float*       Vp = g_V + (size_t)b*Nn*JUn + (size_t)m0*JUn;
    for (int idx = threadIdx.x; idx < 128*32; idx += 256){
        int m = idx >> 5, u = idx & 31;
        float tmp[CNn], msq = 0.f;
        #pragma unroll
        for (int j = 0; j < CNn; j++){
            float v = Sp[(size_t)m*JUn + j*32 + u];
            tmp[j] = v; msq += v*v;
        }
        float fac = sqrtf(msq)/(1.f+msq);
        #pragma unroll
        for (int j = 0; j < CNn; j++)
            Vp[(size_t)m*JUn + j*32 + u] = tmp[j]*fac;
    }
}

// ---------------- T GEMM (TN, m-split): T[s][ik][ju] = (1/1024) sum_{m in split} scU[m][ik]*V[m][ju] ----------------
__global__ __launch_bounds__(256) void k_T(){
    __shared__ float shU[16][IKn];
    __shared__ float shV[16][65];
    int b = blockIdx.z; int n0 = blockIdx.x*64; int mbase = blockIdx.y*128;
    const float* U = g_u + (size_t)b*Nn*IKn;
    const float* V = g_V + (size_t)b*Nn*JUn;
    int tid = threadIdx.x;
    int rg = tid >> 4, cg = tid & 15;   // rows rg*8..+7 of 128, cols cg*4..+3 of 64
    float acc[8][4] = {};
    for (int mc = 0; mc < 128; mc += 16){
        int mm0 = mbase + mc;
        float sc = g_scale[b*GLn + (mm0 >> 8)];
        for (int e = tid; e < 16*IKn; e += 256){
            int m = e >> 7, p = e & 127;
            shU[m][p] = U[(size_t)(mm0+m)*IKn + p]*sc;
        }
        for (int e = tid; e < 16*64; e += 256){
            int m = e >> 6, n = e & 63;
            shV[m][n] = V[(size_t)(mm0+m)*JUn + n0 + n];
        }
        __syncthreads();
        #pragma unroll
        for (int kk = 0; kk < 16; kk++){
            float a[8], c[4];
            #pragma unroll
            for (int i = 0; i < 8; i++) a[i] = shU[kk][rg*8+i];
            #pragma unroll
            for (int j = 0; j < 4; j++) c[j] = shV[kk][cg*4+j];
            #pragma unroll
            for (int i = 0; i < 8; i++)
                #pragma unroll
                for (int j = 0; j < 4; j++)
                    acc[i][j] += a[i]*c[j];
        }
        __syncthreads();
    }
    const float invM = 1.f/1024.f;
    float* Tp = g_T + ((size_t)(b*MS + blockIdx.y)*IKn)*JUn;
    #pragma unroll
    for (int i = 0; i < 8; i++)
        #pragma unroll
        for (int j = 0; j < 4; j++)
            Tp[(size_t)(rg*8+i)*JUn + n0 + cg*4 + j] = acc[i][j]*invM;
}

// ---------------- logits update: blog[i][j] += sum_{u,k} Wg[i,j,u,k]*T[k*32+i][j*32+u] ----------------
__global__ __launch_bounds__(512) void k_update(const float* __restrict__ Wg){
    int b = blockIdx.x, tid = threadIdx.x;   // 512 threads = (i,j)
    int i = tid >> 4, j = tid & 15;
    float a = 0.f;
    #pragma unroll
    for (int k = 0; k < GLn; k++)
        for (int u = 0; u < CSn; u++){
            float t = 0.f;
            #pragma unroll
            for (int s = 0; s < MS; s++)
                t += g_T[((size_t)(b*MS + s)*IKn + k*32 + i)*JUn + j*32 + u];
            a += Wg[((i*CNn+j)*CSn+u)*GLn + k]*t;
        }
    g_blog[b*CSn*CNn + i*CNn + j] += a;
}

// ---------------- last iter: squash + column partial sums (for g = mean_m v) ----------------
__global__ __launch_bounds__(256) void k_gmean(){
    int b = blockIdx.y; int chunk = blockIdx.x; int m0 = chunk*128;
    const float* Sp = g_S + (size_t)b*Nn*JUn + (size_t)m0*JUn;
    __shared__ float fac[128][33];
    int tid = threadIdx.x;
    for (int idx = tid; idx < 128*32; idx += 256){
        int m = idx >> 5, u = idx & 31;
        float msq = 0.f;
        #pragma unroll
        for (int j = 0; j < CNn; j++){
            float v = Sp[(size_t)m*JUn + j*32 + u];
            msq += v*v;
        }
        fac[m][u] = sqrtf(msq)/(1.f+msq);
    }
    __syncthreads();
    for (int n = tid; n < JUn; n += 256){
        int u = n & 31;
        float cs = 0.f;
        for (int m = 0; m < 128; m++)
            cs += Sp[(size_t)m*JUn + n]*fac[m][u];
        g_gpart[(b*8 + chunk)*JUn + n] = cs;
    }
}

// ---------------- aspect stage: attention (hidden cancels) + aspect routing with M collapsed to 1 ----------------
__global__ __launch_bounds__(256) void k_aspect(const float* __restrict__ Wa,
                                                const float* __restrict__ Ws){
    __shared__ float g[CNn][CSn];
    __shared__ float cond[CNn][CSn];
    __shared__ float uh[CNn][NAn][CSn];
    __shared__ float b2[CNn][NAn];
    __shared__ float c2[CNn][NAn];
    __shared__ float s2[NAn][CSn];
    __shared__ float v2[NAn][CSn];
    __shared__ float facu[CSn];
    __shared__ float score[CNn];
    int b = blockIdx.x, tid = threadIdx.x;
    const float invN = 1.f/1024.f;
    for (int e = tid; e < JUn; e += 256){
        float t = 0.f;
        #pragma unroll
        for (int s = 0; s < 8; s++) t += g_gpart[(b*8+s)*JUn + e];
        g[e>>5][e&31] = t*invN;
    }
    __syncthreads();
    if (tid == 0){
        float gw[CNn], mx = -1e30f;
        for (int i = 0; i < CNn; i++){
            float s = 0.f;
            for (int u = 0; u < CSn; u++) s += g[i][u]*Wa[u];
            gw[i] = s; mx = fmaxf(mx, s);
        }
        float sum = 0.f;
        for (int i = 0; i < CNn; i++){ gw[i] = expf(gw[i]-mx); sum += gw[i]; }
        float inv = 1.f/sum;
        for (int i = 0; i < CNn; i++) score[i] = gw[i]*inv;
    }
    __syncthreads();
    for (int e = tid; e < JUn; e += 256)
        cond[e>>5][e&31] = g[e>>5][e&31]*score[e>>5];
    if (tid < 256){ int i = tid >> 4, j = tid & 15; b2[i][j] = 0.f; }
    __syncthreads();
    // u_hat_a[i][j][u] = sum_k Ws[i,j,u,k] * cond[i][k]
    for (int e = tid; e < CNn*NAn*CSn; e += 256){
        int i = e >> 9, j = (e >> 5) & 15, u = e & 31;
        float s = 0.f;
        const float* wrow = Ws + ((size_t)((i*NAn+j)*CSn+u))*CSn;
        #pragma unroll
        for (int k = 0; k < CSn; k++) s += wrow[k]*cond[i][k];
        uh[i][j][u] = s;
    }
    __syncthreads();
    for (int it = 0; it < 3; it++){
        if (tid < CNn){
            int i = tid;
            float mx = -1e30f;
            #pragma unroll
            for (int j = 0; j < NAn; j++) mx = fmaxf(mx, b2[i][j]);
            float sum = 0.f, r[NAn];
            #pragma unroll
            for (int j = 0; j < NAn; j++){ r[j] = expf(b2[i][j]-mx); sum += r[j]; }
            float inv = 1.f/sum;
            #pragma unroll
            for (int j = 0; j < NAn; j++) c2[i][j] = r[j]*inv;
        }
        __syncthreads();
        for (int e = tid; e < NAn*CSn; e += 256){
            int j = e >> 5, u = e & 31;
            float s = 0.f;
            #pragma unroll
            for (int i = 0; i < CNn; i++) s += c2[i][j]*uh[i][j][u];
            s2[j][u] = s;
        }
        __syncthreads();
        if (tid < CSn){
            int u = tid; float ms = 0.f;
            #pragma unroll
            for (int j = 0; j < NAn; j++) ms += s2[j][u]*s2[j][u];
            facu[u] = sqrtf(ms)/(1.f+ms);
        }
        __syncthreads();
        for (int e = tid; e < NAn*CSn; e += 256){
            int j = e >> 5, u = e & 31;
            v2[j][u] = s2[j][u]*facu[u];
        }
        __syncthreads();
        if (it < 2){
            if (tid < 256){
                int i = tid >> 4, j = tid & 15;
                float a = 0.f;
                #pragma unroll
                for (int u = 0; u < CSn; u++) a += uh[i][j][u]*v2[j][u];
                b2[i][j] += a;
            }
            __syncthreads();
        }
    }
    for (int e = tid; e < NAn*CSn; e += 256)
        g_va[b*NAn*CSn + e] = v2[e>>5][e&31];
}

// ---------------- broadcast final v to all S rows ----------------
__global__ __launch_bounds__(256) void k_broadcast(float* __restrict__ out){
    int idx = blockIdx.x*blockDim.x + threadIdx.x;
    if (idx < Bn*Sn*NAn*CSn){
        int b = idx >> 18;                 // 512*512 per batch
        int r = idx & ((Sn*NAn*CSn/ Sn)*Sn - 1); // = idx & 262143
        out[idx] = g_va[b*NAn*CSn + (r & 511)];
    }
}

extern "C" void kernel_launch(void* const* d_in, const int* in_sizes, int n_in,
                              void* d_out, int out_size){
    (void)in_sizes; (void)n_in; (void)out_size;
    const float* ge = (const float*)d_in[0];
    // d_in[1] = hidden: mathematically cancels in the softmax over capsules; never read.
    const float* Wp = (const float*)d_in[2];
    const float* bp = (const float*)d_in[3];
    const float* Wg = (const float*)d_in[4];
    const float* Wa = (const float*)d_in[5];
    const float* Ws = (const float*)d_in[6];
    float* out = (float*)d_out;

    k_init<<<8, 256>>>();
    k_primary<<<dim3(Nn/64, Rn/64, Bn), 256>>>(Wp, bp, ge);
    k_msq<<<Bn*GLn, 256>>>();
    for (int t = 0; t < 3; t++){
        k_route_w<<<Bn, 256>>>(Wg);
        k_route_s<<<dim3(JUn/64, Nn/64, Bn), 256>>>();
        if (t < 2){
            k_squash<<<dim3(Nn/128, Bn), 256>>>();
            k_T<<<dim3(JUn/64, MS, Bn), 256>>>();
            k_update<<<Bn, 512>>>(Wg);
        } else {
            k_gmean<<<dim3(Nn/128, Bn), 256>>>();
        }
    }
    k_aspect<<<Bn, 256>>>(Wa, Ws);
    k_broadcast<<<(Bn*Sn*NAn*CSn + 255)/256, 256>>>(out);
}

// round 2
// speedup vs baseline: 2.9515x; 2.9515x over previous
#include <cuda_runtime.h>
#include <math.h>

#define Bn 4
#define GLn 4
#define Nn 1024
#define CSn 32
#define CNn 16
#define NAn 16
#define Sn 512
#define Rn 128     // GL*CS
#define K1n 512    // GL*GF
#define IKn 128    // CS*GL
#define JUn 512    // CN*CS

// -------- scratch (device globals; no allocations anywhere) --------
__device__ float g_u[Bn*Rn*Nn];        // primary caps pre-squash, [b][r=128][n=1024]
__device__ float g_msqp[Bn*GLn*16];    // squash-norm partials per (b,g,nblk)
__device__ float g_WgT[IKn*JUn];       // permuted Wg: [ik=128][ju=512]
__device__ float g_V[Bn*Nn*JUn];       // routing v
__device__ float g_apart[Bn*8*8*64];   // agreement partials [b][msplit][nblk][i*2+jg]
__device__ float g_blog[Bn*CSn*CNn];   // routing logits
__device__ float g_gpart[Bn*32*JUn];   // column-sum partials of final v
__device__ float g_va[Bn*NAn*CSn];     // aspect routing output

// ---------------- Wg permute: WgT[(k*32+i)*512 + j*32+u] = Wg[((i*16+j)*32+u)*4+k] ----------------
__global__ void k_permW(const float* __restrict__ Wg){
    int idx = blockIdx.x*256 + threadIdx.x;
    if (idx < IKn*JUn){
        int ik = idx >> 9, ju = idx & 511;
        int k = ik >> 5, i = ik & 31, j = ju >> 5, u = ju & 31;
        g_WgT[idx] = Wg[((i*CNn + j)*CSn + u)*GLn + k];
    }
}

// ---------------- primary caps GEMM + squash-norm partials ----------------
__global__ __launch_bounds__(256) void k_primary(const float* __restrict__ Wp,
                                                 const float* __restrict__ bp,
                                                 const float* __restrict__ X){
    __shared__ float shA[16][65];
    __shared__ float shB[16][65];
    __shared__ float red[256];
    int b = blockIdx.z;
    int m0 = blockIdx.y*64, n0 = blockIdx.x*64;
    const float* Xb = X + (size_t)b*K1n*Nn;
    int tid = threadIdx.x;
    int tx = tid & 15, ty = tid >> 4;
    float acc[4][4] = {};
    for (int k0 = 0; k0 < K1n; k0 += 16){
        for (int e = tid; e < 64*16; e += 256){
            int m = e >> 4, k = e & 15;
            shA[k][m] = Wp[(m0+m)*K1n + k0 + k];
        }
        for (int e = tid; e < 16*64; e += 256){
            int k = e >> 6, n = e & 63;
            shB[k][n] = Xb[(size_t)(k0+k)*Nn + n0 + n];
        }
        __syncthreads();
        #pragma unroll
        for (int kk = 0; kk < 16; kk++){
            float a[4], c[4];
            #pragma unroll
            for (int i = 0; i < 4; i++) a[i] = shA[kk][ty*4+i];
            #pragma unroll
            for (int j = 0; j < 4; j++) c[j] = shB[kk][tx*4+j];
            #pragma unroll
            for (int i = 0; i < 4; i++)
                #pragma unroll
                for (int j = 0; j < 4; j++)
                    acc[i][j] += a[i]*c[j];
        }
        __syncthreads();
    }
    float ssq = 0.f;
    #pragma unroll
    for (int i = 0; i < 4; i++){
        int m = m0 + ty*4 + i;
        float bias = bp[m];
        #pragma unroll
        for (int j = 0; j < 4; j++){
            float v = acc[i][j] + bias;
            g_u[(size_t)b*Rn*Nn + (size_t)m*Nn + n0 + tx*4 + j] = v;
            ssq += v*v;
        }
    }
    // per-half (32-row = one GL group) ssq reduction
    red[tid] = ssq; __syncthreads();
    int half = tid >> 7, lid = tid & 127;
    for (int off = 64; off; off >>= 1){
        if (lid < off) red[half*128 + lid] += red[half*128 + lid + off];
        __syncthreads();
    }
    if (lid == 0)
        g_msqp[(b*GLn + (m0 >> 5) + half)*16 + blockIdx.x] = red[half*128];
}

// ---------------- fused routing-s GEMM + squash (+ gpart at iter 2) ----------------
// block: 32 m rows x full 512 ju cols; thread (ty=tid>>5, tx=tid&31):
//   m = m0+ty*4+mm, col = c*32+tx  (so j=c, u=tx -> squash over j is thread-local)
__global__ __launch_bounds__(256) void k_route_sq(int iter){
    __shared__ float buf[16*512];    // B tile; reused as colsum partials at iter 2
    __shared__ float shA[16][33];
    __shared__ float c_sh[32][16];
    __shared__ float sc_sh;
    int b = blockIdx.y;
    int m0 = blockIdx.x*32;
    int tid = threadIdx.x;
    int tx = tid & 31, ty = tid >> 5;
    if (tid == 0){
        int grp = m0 >> 8;
        float s = 0.f;
        #pragma unroll
        for (int t = 0; t < 16; t++) s += g_msqp[(b*GLn + grp)*16 + t];
        sc_sh = sqrtf(s)/(1.f + s);
    }
    if (iter == 0){
        for (int e = tid; e < 512; e += 256) c_sh[e>>4][e&15] = 0.0625f;
    } else if (tid < 32){
        int i = tid;
        float row[CNn], mx = -1e30f;
        #pragma unroll
        for (int j = 0; j < CNn; j++){ row[j] = g_blog[b*512 + i*16 + j]; mx = fmaxf(mx, row[j]); }
        float sum = 0.f;
        #pragma unroll
        for (int j = 0; j < CNn; j++){ row[j] = expf(row[j]-mx); sum += row[j]; }
        float inv = 1.f/sum;
        #pragma unroll
        for (int j = 0; j < CNn; j++) c_sh[i][j] = row[j]*inv;
    }
    __syncthreads();
    float sc = sc_sh;
    const float* U = g_u + (size_t)b*Nn*IKn;
    float acc[4][16] = {};
    for (int k0 = 0; k0 < IKn; k0 += 16){
        for (int e = tid; e < 512; e += 256){
            int m = e >> 4, k = e & 15;
            shA[k][m] = U[(size_t)(m0+m)*IKn + k0 + k]*sc;
        }
        for (int e = tid; e < 8192; e += 256){
            int k = e >> 9, n = e & 511;
            buf[e] = g_WgT[(size_t)(k0+k)*JUn + n] * c_sh[(k0+k) & 31][n >> 5];
        }
        __syncthreads();
        #pragma unroll
        for (int kk = 0; kk < 16; kk++){
            float a[4];
            #pragma unroll
            for (int mm = 0; mm < 4; mm++) a[mm] = shA[kk][ty*4+mm];
            #pragma unroll
            for (int c = 0; c < 16; c++){
                float bb = buf[kk*512 + c*32 + tx];
                #pragma unroll
                for (int mm = 0; mm < 4; mm++)
                    acc[mm][c] += a[mm]*bb;
            }
        }
        __syncthreads();
    }
    // squash over j (thread-local: j == c)
    float fac[4];
    #pragma unroll
    for (int mm = 0; mm < 4; mm++){
        float msq = 0.f;
        #pragma unroll
        for (int c = 0; c < 16; c++) msq += acc[mm][c]*acc[mm][c];
        fac[mm] = sqrtf(msq)/(1.f + msq);
    }
    if (iter < 2){
        float* Vp = g_V + (size_t)b*Nn*JUn;
        #pragma unroll
        for (int mm = 0; mm < 4; mm++){
            size_t rb = (size_t)(m0 + ty*4 + mm)*JUn;
            #pragma unroll
            for (int c = 0; c < 16; c++)
                Vp[rb + c*32 + tx] = acc[mm][c]*fac[mm];
        }
    } else {
        // column sums of v over this block's 32 m
        float cs[16];
        #pragma unroll
        for (int c = 0; c < 16; c++){
            float s = 0.f;
            #pragma unroll
            for (int mm = 0; mm < 4; mm++) s += acc[mm][c]*fac[mm];
            cs[c] = s;
        }
        __syncthreads();
        #pragma unroll
        for (int c = 0; c < 16; c++) buf[ty*512 + c*32 + tx] = cs[c];
        __syncthreads();
        for (int col = tid; col < 512; col += 256){
            float s = 0.f;
            #pragma unroll
            for (int w = 0; w < 8; w++) s += buf[w*512 + col];
            g_gpart[((size_t)b*32 + blockIdx.x)*JUn + col] = s;
        }
    }
}

// ---------------- fused T GEMM + agreement partials ----------------
// grid (8 nblk, 8 msplit, Bn); block computes T tile [128 ik x 64 ju] in regs,
// contracts against WgT, emits 64 partial logits (i, jg).
__global__ __launch_bounds__(256) void k_T_fused(){
    __shared__ float shU[16][128];
    __shared__ float shV[16][64];
    __shared__ float stage[16][16][8];
    __shared__ float sc_sh;
    int b = blockIdx.z, nblk = blockIdx.x, msb = blockIdx.y;
    int n0 = nblk*64, mbase = msb*128;
    int tid = threadIdx.x;
    int rg = tid >> 4, cg = tid & 15;
    if (tid == 0){
        int grp = mbase >> 8;
        float s = 0.f;
        #pragma unroll
        for (int t = 0; t < 16; t++) s += g_msqp[(b*GLn + grp)*16 + t];
        sc_sh = sqrtf(s)/(1.f + s);
    }
    __syncthreads();
    float sc = sc_sh;
    const float* U = g_u + (size_t)b*Nn*IKn;
    const float* V = g_V + (size_t)b*Nn*JUn;
    float acc[8][4] = {};
    for (int mc = 0; mc < 128; mc += 16){
        int mm0 = mbase + mc;
        for (int e = tid; e < 2048; e += 256){
            int m = e >> 7, p = e & 127;
            shU[m][p] = U[(size_t)(mm0+m)*IKn + p]*sc;
        }
        for (int e = tid; e < 1024; e += 256){
            int m = e >> 6, n = e & 63;
            shV[m][n] = V[(size_t)(mm0+m)*JUn + n0 + n];
        }
        __syncthreads();
        #pragma unroll
        for (int kk = 0; kk < 16; kk++){
            float a[8];
            #pragma unroll
            for (int i = 0; i < 8; i++) a[i] = shU[kk][rg*8+i];
            float4 c4 = *(float4*)&shV[kk][cg*4];
            #pragma unroll
            for (int i = 0; i < 8; i++){
                acc[i][0] += a[i]*c4.x;
                acc[i][1] += a[i]*c4.y;
                acc[i][2] += a[i]*c4.z;
                acc[i][3] += a[i]*c4.w;
            }
        }
        __syncthreads();
    }
    // agreement: dot T tile with WgT
    const float invM = 1.f/1024.f;
    #pragma unroll
    for (int i8 = 0; i8 < 8; i8++){
        int row = rg*8 + i8;
        const float* w = g_WgT + (size_t)row*JUn + n0 + cg*4;
        float s = acc[i8][0]*w[0] + acc[i8][1]*w[1] + acc[i8][2]*w[2] + acc[i8][3]*w[3];
        stage[rg][cg][i8] = s*invM;
    }
    __syncthreads();
    if (tid < 64){
        int i = tid >> 1, jg = tid & 1;
        float s = 0.f;
        #pragma unroll
        for (int r4 = 0; r4 < 4; r4++){
            int rgp = (i >> 3) + r4*4;
            #pragma unroll
            for (int c8 = 0; c8 < 8; c8++)
                s += stage[rgp][jg*8 + c8][i & 7];
        }
        g_apart[((b*8 + msb)*8 + nblk)*64 + i*2 + jg] = s;
    }
}

// ---------------- fold agreement partials into blog ----------------
__global__ void k_fold(int iter){
    int b = blockIdx.x, tid = threadIdx.x;     // 512 threads = (i,j)
    int i = tid >> 4, j = tid & 15;
    float a = 0.f;
    #pragma unroll
    for (int s = 0; s < 8; s++)
        a += g_apart[((b*8 + s)*8 + (j >> 1))*64 + i*2 + (j & 1)];
    float old = (iter == 0) ? 0.f : g_blog[b*512 + tid];
    g_blog[b*512 + tid] = old + a;
}

// ---------------- aspect stage (hidden cancels; M collapses to 1) ----------------
__global__ __launch_bounds__(256) void k_aspect(const float* __restrict__ Wa,
                                                const float* __restrict__ Ws){
    __shared__ float g[CNn][CSn];
    __shared__ float cond[CNn][CSn];
    __shared__ float uh[CNn][NAn][CSn];
    __shared__ float b2[CNn][NAn];
    __shared__ float c2[CNn][NAn];
    __shared__ float s2[NAn][CSn];
    __shared__ float v2[NAn][CSn];
    __shared__ float facu[CSn];
    __shared__ float score[CNn];
    int b = blockIdx.x, tid = threadIdx.x;
    const float invN = 1.f/1024.f;
    for (int e = tid; e < JUn; e += 256){
        float t = 0.f;
        #pragma unroll
        for (int s = 0; s < 32; s++) t += g_gpart[((size_t)b*32 + s)*JUn + e];
        g[e>>5][e&31] = t*invN;
    }
    __syncthreads();
    if (tid == 0){
        float gw[CNn], mx = -1e30f;
        for (int i = 0; i < CNn; i++){
            float s = 0.f;
            for (int u = 0; u < CSn; u++) s += g[i][u]*Wa[u];
            gw[i] = s; mx = fmaxf(mx, s);
        }
        float sum = 0.f;
        for (int i = 0; i < CNn; i++){ gw[i] = expf(gw[i]-mx); sum += gw[i]; }
        float inv = 1.f/sum;
        for (int i = 0; i < CNn; i++) score[i] = gw[i]*inv;
    }
    __syncthreads();
    for (int e = tid; e < JUn; e += 256)
        cond[e>>5][e&31] = g[e>>5][e&31]*score[e>>5];
    if (tid < 256){ int i = tid >> 4, j = tid & 15; b2[i][j] = 0.f; }
    __syncthreads();
    for (int e = tid; e < CNn*NAn*CSn; e += 256){
        int i = e >> 9, j = (e >> 5) & 15, u = e & 31;
        float s = 0.f;
        const float* wrow = Ws + ((size_t)((i*NAn+j)*CSn+u))*CSn;
        #pragma unroll
        for (int k = 0; k < CSn; k++) s += wrow[k]*cond[i][k];
        uh[i][j][u] = s;
    }
    __syncthreads();
    for (int it = 0; it < 3; it++){
        if (tid < CNn){
            int i = tid;
            float mx = -1e30f;
            #pragma unroll
            for (int j = 0; j < NAn; j++) mx = fmaxf(mx, b2[i][j]);
            float sum = 0.f, r[NAn];
            #pragma unroll
            for (int j = 0; j < NAn; j++){ r[j] = expf(b2[i][j]-mx); sum += r[j]; }
            float inv = 1.f/sum;
            #pragma unroll
            for (int j = 0; j < NAn; j++) c2[i][j] = r[j]*inv;
        }
        __syncthreads();
        for (int e = tid; e < NAn*CSn; e += 256){
            int j = e >> 5, u = e & 31;
            float s = 0.f;
            #pragma unroll
            for (int i = 0; i < CNn; i++) s += c2[i][j]*uh[i][j][u];
            s2[j][u] = s;
        }
        __syncthreads();
        if (tid < CSn){
            int u = tid; float ms = 0.f;
            #pragma unroll
            for (int j = 0; j < NAn; j++) ms += s2[j][u]*s2[j][u];
            facu[u] = sqrtf(ms)/(1.f+ms);
        }
        __syncthreads();
        for (int e = tid; e < NAn*CSn; e += 256){
            int j = e >> 5, u = e & 31;
            v2[j][u] = s2[j][u]*facu[u];
        }
        __syncthreads();
        if (it < 2){
            if (tid < 256){
                int i = tid >> 4, j = tid & 15;
                float a = 0.f;
                #pragma unroll
                for (int u = 0; u < CSn; u++) a += uh[i][j][u]*v2[j][u];
                b2[i][j] += a;
            }
            __syncthreads();
        }
    }
    for (int e = tid; e < NAn*CSn; e += 256)
        g_va[b*NAn*CSn + e] = v2[e>>5][e&31];
}

// ---------------- broadcast final v to all S rows ----------------
__global__ __launch_bounds__(256) void k_broadcast(float* __restrict__ out){
    int idx = blockIdx.x*blockDim.x + threadIdx.x;
    if (idx < Bn*Sn*NAn*CSn){
        int b = idx >> 18;
        out[idx] = g_va[b*NAn*CSn + (idx & 511)];
    }
}

extern "C" void kernel_launch(void* const* d_in, const int* in_sizes, int n_in,
                              void* d_out, int out_size){
    (void)in_sizes; (void)n_in; (void)out_size;
    const float* ge = (const float*)d_in[0];
    // d_in[1] = hidden: cancels exactly in the softmax over capsules; never read.
    const float* Wp = (const float*)d_in[2];
    const float* bp = (const float*)d_in[3];
    const float* Wg = (const float*)d_in[4];
    const float* Wa = (const float*)d_in[5];
    const float* Ws = (const float*)d_in[6];
    float* out = (float*)d_out;

    k_permW<<<256, 256>>>(Wg);
    k_primary<<<dim3(16, 2, Bn), 256>>>(Wp, bp, ge);
    for (int t = 0; t < 3; t++){
        k_route_sq<<<dim3(32, Bn), 256>>>(t);
        if (t < 2){
            k_T_fused<<<dim3(8, 8, Bn), 256>>>();
            k_fold<<<Bn, 512>>>(t);
        }
    }
    k_aspect<<<Bn, 256>>>(Wa, Ws);
    k_broadcast<<<(Bn*Sn*NAn*CSn + 255)/256, 256>>>(out);
}